// round 14
// baseline (speedup 1.0000x reference)
#include <cuda_runtime.h>
#include <cstdint>

#define N_NODES 100000
#define F_IN    512
#define HID     16
#define N_CLS   40
#define E_EDGES 3200000
#define BKT     96             // bucket capacity per node (P(overflow) ~ 1e-18)

// packed fp32x2 ops (Blackwell)
#define FMA2(d, a, b, c) \
    asm("fma.rn.f32x2 %0, %1, %2, %3;" : "=l"(d) : "l"(a), "l"(b), "l"(c))

// cp.async helpers
__device__ __forceinline__ void cp_async16(uint32_t saddr, const void* gptr) {
    asm volatile("cp.async.cg.shared.global [%0], [%1], 16;"
                 :: "r"(saddr), "l"(gptr));
}
#define CP_COMMIT() asm volatile("cp.async.commit_group;" ::: "memory")
#define CP_WAIT(n)  asm volatile("cp.async.wait_group %0;" :: "n"(n) : "memory")

// -------- device scratch (no dynamic allocation allowed) --------
__device__ __align__(16) float g_dinv[N_NODES];
__device__ __align__(16) int   g_cur [N_NODES];
__device__ __align__(16) int   g_csr [N_NODES * BKT];    // src-only buckets
__device__ __align__(16) float g_Wt  [HID * F_IN];       // W1 transposed [j][k]
__device__ __align__(16) float g_h1  [N_NODES * HID];    // pre-scaled: h1*dinv
__device__ __align__(16) float g_out1[N_NODES * HID];    // pre-scaled: out1*dinv

// -------- bucket cursor init --------
__global__ void init_cur_kernel() {
    int i = blockIdx.x * blockDim.x + threadIdx.x;
    if (i < N_NODES) g_cur[i] = i * BKT;
}

// -------- CSR fill: src index per dst bucket --------
__global__ void fill_kernel(const int* __restrict__ ei) {
    int e = blockIdx.x * blockDim.x + threadIdx.x;
    if (e >= E_EDGES) return;
    int s = ei[e];
    int d = ei[E_EDGES + e];
    int pos = atomicAdd(&g_cur[d], 1);
    g_csr[pos] = s;
}

// -------- dinv from bucket fill level + W1 transpose (piggy-backed) --------
__global__ void dinv_kernel(const float* __restrict__ W1) {
    int i = blockIdx.x * blockDim.x + threadIdx.x;
    if (i < F_IN * HID) {
        int k = i >> 4;
        int j = i & 15;
        g_Wt[j * F_IN + k] = W1[i];
    }
    if (i < N_NODES)
        g_dinv[i] = rsqrtf((float)(g_cur[i] - i * BKT + 1));
}

// -------- GEMM1: hs = (x @ W1) * dinv --------
// cp.async double-buffered x tiles; W read from g_Wt via L1-resident LDG.128.
// smem = 32 KB only -> ~6 blocks/SM.
#define G1_ROWS 64
#define G1_KC   64
#define G1_NT   (F_IN / G1_KC)              // 8 tiles

__global__ __launch_bounds__(256) void gemm1_kernel(const float* __restrict__ x) {
    __shared__ __align__(16) float xs[2][G1_ROWS * G1_KC];   // 32 KB

    int row0 = blockIdx.x * G1_ROWS;

    // async stage of one x tile (64 rows x 64 cols) into buf
    auto stage = [&](float* buf, int kc) {
        #pragma unroll
        for (int i = threadIdx.x; i < G1_ROWS * (G1_KC / 4); i += 256) {
            int row = i >> 4;                // 16 float4 per row
            int c4  = i & 15;
            int grow = row0 + row;
            if (grow >= N_NODES) grow = N_NODES - 1;   // clamp (stores guarded)
            cp_async16((uint32_t)__cvta_generic_to_shared(&buf[row * G1_KC + c4 * 4]),
                       x + (size_t)grow * F_IN + kc + c4 * 4);
        }
    };

    stage(xs[0], 0);
    CP_COMMIT();

    int warp = threadIdx.x >> 5;
    int lane = threadIdx.x & 31;
    int j    = lane & 15;
    int half = lane >> 4;

    unsigned long long acc[8];
    #pragma unroll
    for (int r = 0; r < 8; r++) acc[r] = 0ull;

    #pragma unroll
    for (int t = 0; t < G1_NT; t++) {
        float* cur = xs[t & 1];
        if (t < G1_NT - 1) {
            stage(xs[(t & 1) ^ 1], (t + 1) * G1_KC);
            CP_COMMIT();
            CP_WAIT(1);          // tile t's group complete
        } else {
            CP_WAIT(0);
        }
        __syncthreads();

        const float* wbase = &g_Wt[j * F_IN + t * G1_KC + half * 32];
        const float* xbase = &cur[warp * 8 * G1_KC + half * 32];

        #pragma unroll
        for (int kk = 0; kk < 32; kk += 4) {
            ulonglong2 w2 = *reinterpret_cast<const ulonglong2*>(wbase + kk);
            #pragma unroll
            for (int r = 0; r < 8; r++) {
                ulonglong2 xv = *reinterpret_cast<const ulonglong2*>(
                    xbase + r * G1_KC + kk);
                FMA2(acc[r], xv.x, w2.x, acc[r]);
                FMA2(acc[r], xv.y, w2.y, acc[r]);
            }
        }
        __syncthreads();         // buffer safe to overwrite next iteration
    }

    // finish: unpack pair, add halves via shfl, scale by dinv, store
    #pragma unroll
    for (int r = 0; r < 8; r++) {
        float lo = __uint_as_float((unsigned)acc[r]);
        float hi = __uint_as_float((unsigned)(acc[r] >> 32));
        float a = lo + hi;
        a += __shfl_xor_sync(0xffffffffu, a, 16);
        int grow = row0 + warp * 8 + r;
        if (lane < 16 && grow < N_NODES)
            g_h1[(size_t)grow * HID + j] = a * g_dinv[grow];
    }
}

// -------- edge accumulation: src-only buckets, 16 edges/iter main loop ----
// lane layout: j = lane&15, p = lane>>4.
__device__ __forceinline__ float edge_accum(const float* __restrict__ h,
                                            int beg, int end, int j, int p) {
    float a0 = 0.f, a1 = 0.f, a2 = 0.f, a3 = 0.f;
    float a4 = 0.f, a5 = 0.f, a6 = 0.f, a7 = 0.f;
    int e = beg;
    for (; e + 15 < end; e += 16) {            // 8 edges per p-slot in flight
        int4 v0 = *reinterpret_cast<const int4*>(&g_csr[e + p * 4]);
        int4 v1 = *reinterpret_cast<const int4*>(&g_csr[e + 8 + p * 4]);
        a0 += h[(size_t)v0.x * HID + j];
        a1 += h[(size_t)v0.y * HID + j];
        a2 += h[(size_t)v0.z * HID + j];
        a3 += h[(size_t)v0.w * HID + j];
        a4 += h[(size_t)v1.x * HID + j];
        a5 += h[(size_t)v1.y * HID + j];
        a6 += h[(size_t)v1.z * HID + j];
        a7 += h[(size_t)v1.w * HID + j];
    }
    for (; e + 7 < end; e += 8) {              // 4 edges per p-slot
        int4 v = *reinterpret_cast<const int4*>(&g_csr[e + p * 4]);
        a0 += h[(size_t)v.x * HID + j];
        a1 += h[(size_t)v.y * HID + j];
        a2 += h[(size_t)v.z * HID + j];
        a3 += h[(size_t)v.w * HID + j];
    }
    for (int t = e + p; t < end; t += 2)       // 0-7 tail edges
        a0 += h[(size_t)g_csr[t] * HID + j];
    float acc = ((a0 + a1) + (a2 + a3)) + ((a4 + a5) + (a6 + a7));
    acc += __shfl_xor_sync(0xffffffffu, acc, 16);   // combine p-slots
    return acc;                                      // full sum on all lanes
}

// -------- layer-1: out1s = relu(dinv*(sum+hs[d]) + b1) * dinv --------
__global__ void gather1_kernel(const float* __restrict__ b1) {
    int node = (blockIdx.x * blockDim.x + threadIdx.x) >> 5;
    if (node >= N_NODES) return;
    int lane = threadIdx.x & 31;
    int j = lane & 15;
    int p = lane >> 4;

    float sum = edge_accum(g_h1, node * BKT, g_cur[node], j, p);
    sum += g_h1[(size_t)node * HID + j];      // self loop (hs[d])
    float dv = g_dinv[node];
    float o = fmaxf(fmaf(dv, sum, b1[j]), 0.f) * dv;
    if (p == 0)
        g_out1[(size_t)node * HID + j] = o;
}

// -------- layer-2 aggregation fused with GEMM2 + bias + log_softmax ------
__global__ void gather2_softmax_kernel(const float* __restrict__ W2,
                                       const float* __restrict__ b2,
                                       float* __restrict__ out) {
    __shared__ float W2s[HID * N_CLS];
    __shared__ float b2s[N_CLS];
    for (int i = threadIdx.x; i < HID * N_CLS; i += blockDim.x) W2s[i] = W2[i];
    if (threadIdx.x < N_CLS) b2s[threadIdx.x] = b2[threadIdx.x];
    __syncthreads();

    int node = (blockIdx.x * blockDim.x + threadIdx.x) >> 5;
    if (node >= N_NODES) return;
    int lane = threadIdx.x & 31;
    int j = lane & 15;
    int p = lane >> 4;

    float sum = edge_accum(g_out1, node * BKT, g_cur[node], j, p);
    sum += g_out1[(size_t)node * HID + j];    // self loop (out1s[d])
    float av = g_dinv[node] * sum;            // full agg on all lanes

    // av[j] replicated on lanes j and j+16. mat-vec 16x40 + log_softmax.
    bool act = lane < 20;
    int  j0  = act ? lane : 0;

    float z0 = 0.f, z1 = 0.f;
    #pragma unroll
    for (int k = 0; k < HID; k++) {
        float ak = __shfl_sync(0xffffffffu, av, k);   // lane k holds av[k]
        z0 = fmaf(ak, W2s[k * N_CLS + j0],      z0);
        z1 = fmaf(ak, W2s[k * N_CLS + j0 + 20], z1);
    }
    z0 += b2s[j0];
    z1 += b2s[j0 + 20];

    float m = act ? fmaxf(z0, z1) : -INFINITY;
    #pragma unroll
    for (int o = 16; o; o >>= 1) m = fmaxf(m, __shfl_xor_sync(0xffffffffu, m, o));
    float s = act ? (expf(z0 - m) + expf(z1 - m)) : 0.f;
    #pragma unroll
    for (int o = 16; o; o >>= 1) s += __shfl_xor_sync(0xffffffffu, s, o);
    float lse = m + logf(s);

    if (act) {
        out[(size_t)node * N_CLS + lane]      = z0 - lse;
        out[(size_t)node * N_CLS + lane + 20] = z1 - lse;
    }
}

// -------- launch --------
extern "C" void kernel_launch(void* const* d_in, const int* in_sizes, int n_in,
                              void* d_out, int out_size) {
    const float* x  = (const float*)d_in[0];
    const int*   ei = (const int*)d_in[1];     // int32 (JAX x64 disabled)
    const float* W1 = (const float*)d_in[2];
    const float* b1 = (const float*)d_in[3];
    const float* W2 = (const float*)d_in[4];
    const float* b2 = (const float*)d_in[5];
    float* out = (float*)d_out;

    const int TB = 256;
    int nblk_nodes = (N_NODES + TB - 1) / TB;
    int nblk_edges = (E_EDGES + TB - 1) / TB;
    int nblk_gemm1 = (N_NODES + G1_ROWS - 1) / G1_ROWS;      // 1563
    int nblk_rows  = (N_NODES + (TB / 32) - 1) / (TB / 32);  // warp per node

    init_cur_kernel<<<nblk_nodes, TB>>>();
    fill_kernel<<<nblk_edges, TB>>>(ei);
    dinv_kernel<<<nblk_nodes, TB>>>(W1);

    gemm1_kernel<<<nblk_gemm1, TB>>>(x);   // launch #4 -> profiled

    gather1_kernel<<<nblk_rows, TB>>>(b1);
    gather2_softmax_kernel<<<nblk_rows, TB>>>(W2, b2, out);
}

// round 15
// speedup vs baseline: 1.3131x; 1.3131x over previous
#include <cuda_runtime.h>
#include <cstdint>

#define N_NODES 100000
#define F_IN    512
#define HID     16
#define N_CLS   40
#define E_EDGES 3200000
#define BKT     128            // bucket capacity per node (P(overflow) ~ 1e-40)

// packed fp32x2 ops (Blackwell)
#define FMA2(d, a, b, c) \
    asm("fma.rn.f32x2 %0, %1, %2, %3;" : "=l"(d) : "l"(a), "l"(b), "l"(c))

// cp.async helpers
__device__ __forceinline__ void cp_async16(uint32_t saddr, const void* gptr) {
    asm volatile("cp.async.cg.shared.global [%0], [%1], 16;"
                 :: "r"(saddr), "l"(gptr));
}
#define CP_COMMIT() asm volatile("cp.async.commit_group;" ::: "memory")
#define CP_WAIT(n)  asm volatile("cp.async.wait_group %0;" :: "n"(n) : "memory")

// -------- device scratch (no dynamic allocation allowed) --------
__device__ __align__(16) float g_dinv[N_NODES];
__device__ __align__(16) int   g_cur [N_NODES];
__device__ __align__(16) int   g_csr [N_NODES * BKT];    // src-only buckets
__device__ __align__(16) float g_h1  [N_NODES * HID];    // pre-scaled: h1*dinv
__device__ __align__(16) float g_out1[N_NODES * HID];    // pre-scaled: out1*dinv

// -------- bucket cursor init --------
__global__ void init_cur_kernel() {
    int i = blockIdx.x * blockDim.x + threadIdx.x;
    if (i < N_NODES) g_cur[i] = i * BKT;
}

// -------- CSR fill: src index per dst bucket (2 edges/thread) --------
__global__ void fill_kernel(const int* __restrict__ ei) {
    int t = blockIdx.x * blockDim.x + threadIdx.x;
    int e = t * 2;
    if (e >= E_EDGES) return;
    int2 s2 = *reinterpret_cast<const int2*>(&ei[e]);
    int2 d2 = *reinterpret_cast<const int2*>(&ei[E_EDGES + e]);
    int p0 = atomicAdd(&g_cur[d2.x], 1);
    g_csr[p0] = s2.x;
    int p1 = atomicAdd(&g_cur[d2.y], 1);
    g_csr[p1] = s2.y;
}

// -------- dinv from bucket fill level (deg = edges + self loop) --------
__global__ void dinv_kernel() {
    int i = blockIdx.x * blockDim.x + threadIdx.x;
    if (i < N_NODES)
        g_dinv[i] = rsqrtf((float)(g_cur[i] - i * BKT + 1));
}

// -------- GEMM1: hs = (x @ W1) * dinv ; cp.async double-buffered x tiles ----
#define G1_ROWS 64
#define G1_KC   64
#define G1_NT   (F_IN / G1_KC)              // 8 tiles
#define WS_STRIDE 516                       // conflict-free LDS.128 per-j rows
#define G1_SMEM ((HID * WS_STRIDE + 2 * G1_ROWS * G1_KC) * 4)   // 65792 B

__global__ __launch_bounds__(256) void gemm1_kernel(const float* __restrict__ x,
                                                    const float* __restrict__ W1) {
    extern __shared__ float smem[];
    float* Ws  = smem;                        // [16][516]
    float* xs0 = smem + HID * WS_STRIDE;      // [64][64]
    float* xs1 = xs0 + G1_ROWS * G1_KC;

    int row0 = blockIdx.x * G1_ROWS;

    // stage full W (transposed) once — regular stores, covered by first sync
    for (int i = threadIdx.x; i < F_IN * HID; i += 256) {
        int k = i >> 4;
        int j = i & 15;
        Ws[j * WS_STRIDE + k] = W1[i];
    }

    // async stage of one x tile (64 rows x 64 cols) into buf
    auto stage = [&](float* buf, int kc) {
        #pragma unroll
        for (int i = threadIdx.x; i < G1_ROWS * (G1_KC / 4); i += 256) {
            int row = i >> 4;                // 16 float4 per row
            int c4  = i & 15;
            int grow = row0 + row;
            if (grow >= N_NODES) grow = N_NODES - 1;   // clamp (stores guarded)
            cp_async16((uint32_t)__cvta_generic_to_shared(&buf[row * G1_KC + c4 * 4]),
                       x + (size_t)grow * F_IN + kc + c4 * 4);
        }
    };

    stage(xs0, 0);
    CP_COMMIT();

    int warp = threadIdx.x >> 5;
    int lane = threadIdx.x & 31;
    int j    = lane & 15;
    int half = lane >> 4;

    unsigned long long acc[8];
    #pragma unroll
    for (int r = 0; r < 8; r++) acc[r] = 0ull;

    #pragma unroll
    for (int t = 0; t < G1_NT; t++) {
        float* cur = (t & 1) ? xs1 : xs0;
        if (t < G1_NT - 1) {
            stage((t & 1) ? xs0 : xs1, (t + 1) * G1_KC);
            CP_COMMIT();
            CP_WAIT(1);          // tile t's group complete
        } else {
            CP_WAIT(0);
        }
        __syncthreads();

        const float* wbase = &Ws[j * WS_STRIDE + t * G1_KC + half * 32];
        const float* xbase = &cur[warp * 8 * G1_KC + half * 32];

        #pragma unroll
        for (int kk = 0; kk < 32; kk += 4) {
            ulonglong2 w2 = *reinterpret_cast<const ulonglong2*>(wbase + kk);
            #pragma unroll
            for (int r = 0; r < 8; r++) {
                ulonglong2 xv = *reinterpret_cast<const ulonglong2*>(
                    xbase + r * G1_KC + kk);
                FMA2(acc[r], xv.x, w2.x, acc[r]);
                FMA2(acc[r], xv.y, w2.y, acc[r]);
            }
        }
        __syncthreads();         // buffer safe to overwrite next iteration
    }

    // finish: unpack pair, add halves via shfl, scale by dinv, store
    #pragma unroll
    for (int r = 0; r < 8; r++) {
        float lo = __uint_as_float((unsigned)acc[r]);
        float hi = __uint_as_float((unsigned)(acc[r] >> 32));
        float a = lo + hi;
        a += __shfl_xor_sync(0xffffffffu, a, 16);
        int grow = row0 + warp * 8 + r;
        if (lane < 16 && grow < N_NODES)
            g_h1[(size_t)grow * HID + j] = a * g_dinv[grow];
    }
}

// -------- edge accumulation: src-only buckets, int4 + next-iter prefetch ---
// lane layout: j = lane&15, p = lane>>4. Each p-slot handles 4 edges/int4.
__device__ __forceinline__ float edge_accum(const float* __restrict__ h,
                                            int beg, int end, int j, int p) {
    float a0 = 0.f, a1 = 0.f, a2 = 0.f, a3 = 0.f;
    int e = beg;
    if (e + 7 < end) {
        int4 v = *reinterpret_cast<const int4*>(&g_csr[e + p * 4]);
        for (e += 8; e + 7 < end; e += 8) {
            int4 vn = *reinterpret_cast<const int4*>(&g_csr[e + p * 4]); // prefetch
            a0 += h[(size_t)v.x * HID + j];
            a1 += h[(size_t)v.y * HID + j];
            a2 += h[(size_t)v.z * HID + j];
            a3 += h[(size_t)v.w * HID + j];
            v = vn;
        }
        a0 += h[(size_t)v.x * HID + j];
        a1 += h[(size_t)v.y * HID + j];
        a2 += h[(size_t)v.z * HID + j];
        a3 += h[(size_t)v.w * HID + j];
    }
    for (int t = e + p; t < end; t += 2)       // 0-7 tail edges
        a0 += h[(size_t)g_csr[t] * HID + j];
    float acc = (a0 + a1) + (a2 + a3);
    acc += __shfl_xor_sync(0xffffffffu, acc, 16);   // combine p-slots
    return acc;                                      // full sum on all lanes
}

// -------- layer-1: out1s = relu(dinv*(sum+hs[d]) + b1) * dinv --------
__global__ void gather1_kernel(const float* __restrict__ b1) {
    int node = (blockIdx.x * blockDim.x + threadIdx.x) >> 5;
    if (node >= N_NODES) return;
    int lane = threadIdx.x & 31;
    int j = lane & 15;
    int p = lane >> 4;

    float sum = edge_accum(g_h1, node * BKT, g_cur[node], j, p);
    sum += g_h1[(size_t)node * HID + j];      // self loop (hs[d])
    float dv = g_dinv[node];
    float o = fmaxf(fmaf(dv, sum, b1[j]), 0.f) * dv;
    if (p == 0)
        g_out1[(size_t)node * HID + j] = o;
}

// -------- layer-2 aggregation fused with GEMM2 + bias + log_softmax ------
__global__ void gather2_softmax_kernel(const float* __restrict__ W2,
                                       const float* __restrict__ b2,
                                       float* __restrict__ out) {
    __shared__ float W2s[HID * N_CLS];
    __shared__ float b2s[N_CLS];
    for (int i = threadIdx.x; i < HID * N_CLS; i += blockDim.x) W2s[i] = W2[i];
    if (threadIdx.x < N_CLS) b2s[threadIdx.x] = b2[threadIdx.x];
    __syncthreads();

    int node = (blockIdx.x * blockDim.x + threadIdx.x) >> 5;
    if (node >= N_NODES) return;
    int lane = threadIdx.x & 31;
    int j = lane & 15;
    int p = lane >> 4;

    float sum = edge_accum(g_out1, node * BKT, g_cur[node], j, p);
    sum += g_out1[(size_t)node * HID + j];    // self loop (out1s[d])
    float av = g_dinv[node] * sum;            // full agg on all lanes

    // av[j] replicated on lanes j and j+16. mat-vec 16x40 + log_softmax.
    bool act = lane < 20;
    int  j0  = act ? lane : 0;

    float z0 = 0.f, z1 = 0.f;
    #pragma unroll
    for (int k = 0; k < HID; k++) {
        float ak = __shfl_sync(0xffffffffu, av, k);   // lane k holds av[k]
        z0 = fmaf(ak, W2s[k * N_CLS + j0],      z0);
        z1 = fmaf(ak, W2s[k * N_CLS + j0 + 20], z1);
    }
    z0 += b2s[j0];
    z1 += b2s[j0 + 20];

    float m = act ? fmaxf(z0, z1) : -INFINITY;
    #pragma unroll
    for (int o = 16; o; o >>= 1) m = fmaxf(m, __shfl_xor_sync(0xffffffffu, m, o));
    float s = act ? (expf(z0 - m) + expf(z1 - m)) : 0.f;
    #pragma unroll
    for (int o = 16; o; o >>= 1) s += __shfl_xor_sync(0xffffffffu, s, o);
    float lse = m + logf(s);

    if (act) {
        out[(size_t)node * N_CLS + lane]      = z0 - lse;
        out[(size_t)node * N_CLS + lane + 20] = z1 - lse;
    }
}

// -------- launch --------
extern "C" void kernel_launch(void* const* d_in, const int* in_sizes, int n_in,
                              void* d_out, int out_size) {
    const float* x  = (const float*)d_in[0];
    const int*   ei = (const int*)d_in[1];     // int32 (JAX x64 disabled)
    const float* W1 = (const float*)d_in[2];
    const float* b1 = (const float*)d_in[3];
    const float* W2 = (const float*)d_in[4];
    const float* b2 = (const float*)d_in[5];
    float* out = (float*)d_out;

    cudaFuncSetAttribute(gemm1_kernel,
                         cudaFuncAttributeMaxDynamicSharedMemorySize, G1_SMEM);

    const int TB = 256;
    int nblk_nodes = (N_NODES + TB - 1) / TB;
    int nblk_edges2 = (E_EDGES / 2 + TB - 1) / TB;
    int nblk_gemm1 = (N_NODES + G1_ROWS - 1) / G1_ROWS;      // 1563
    int nblk_rows  = (N_NODES + (TB / 32) - 1) / (TB / 32);  // warp per node

    init_cur_kernel<<<nblk_nodes, TB>>>();
    fill_kernel<<<nblk_edges2, TB>>>(ei);
    dinv_kernel<<<nblk_nodes, TB>>>();

    gemm1_kernel<<<nblk_gemm1, TB, G1_SMEM>>>(x, W1);   // launch #4 -> profiled

    gather1_kernel<<<nblk_rows, TB>>>(b1);
    gather2_softmax_kernel<<<nblk_rows, TB>>>(W2, b2, out);
}

// round 16
// speedup vs baseline: 1.4049x; 1.0699x over previous
#include <cuda_runtime.h>
#include <cuda_fp16.h>
#include <cstdint>

#define N_NODES 100000
#define F_IN    512
#define HID     16
#define N_CLS   40
#define E_EDGES 3200000
#define BKT     128            // bucket capacity per node (P(overflow) ~ 1e-40)

// packed fp32x2 ops (Blackwell)
#define FMA2(d, a, b, c) \
    asm("fma.rn.f32x2 %0, %1, %2, %3;" : "=l"(d) : "l"(a), "l"(b), "l"(c))

// cp.async helpers
__device__ __forceinline__ void cp_async16(uint32_t saddr, const void* gptr) {
    asm volatile("cp.async.cg.shared.global [%0], [%1], 16;"
                 :: "r"(saddr), "l"(gptr));
}
#define CP_COMMIT() asm volatile("cp.async.commit_group;" ::: "memory")
#define CP_WAIT(n)  asm volatile("cp.async.wait_group %0;" :: "n"(n) : "memory")

// -------- device scratch (no dynamic allocation allowed) --------
__device__ __align__(16) float  g_dinv[N_NODES];
__device__ __align__(16) int    g_cur [N_NODES];     // zero-init; reset each pass
__device__ __align__(16) int    g_cnt [N_NODES];
__device__ __align__(16) int    g_csr [N_NODES * BKT];   // src-only buckets
__device__ __align__(16) __half g_h1  [N_NODES * HID];   // fp16, pre-scaled h1*dinv
__device__ __align__(16) __half g_out1[N_NODES * HID];   // fp16, pre-scaled out1*dinv

// -------- CSR fill: src index per dst bucket (zero-based cursor) --------
__global__ void fill_kernel(const int* __restrict__ ei) {
    int e = blockIdx.x * blockDim.x + threadIdx.x;
    if (e >= E_EDGES) return;
    int s = ei[e];
    int d = ei[E_EDGES + e];
    int cnt = atomicAdd(&g_cur[d], 1);
    g_csr[d * BKT + cnt] = s;
}

// -------- dinv + count snapshot + cursor reset (for next graph replay) ----
__global__ void dinv_kernel() {
    int i = blockIdx.x * blockDim.x + threadIdx.x;
    if (i < N_NODES) {
        int cnt = g_cur[i];
        g_cnt[i] = cnt;
        g_cur[i] = 0;                          // ready for next replay
        g_dinv[i] = rsqrtf((float)(cnt + 1));  // + self loop
    }
}

// -------- GEMM1: hs = (x @ W1) * dinv ; cp.async double-buffered x tiles ----
#define G1_ROWS 64
#define G1_KC   64
#define G1_NT   (F_IN / G1_KC)              // 8 tiles
#define WS_STRIDE 516                       // conflict-free LDS.128 per-j rows
#define G1_SMEM ((HID * WS_STRIDE + 2 * G1_ROWS * G1_KC) * 4)   // 65792 B

__global__ __launch_bounds__(256) void gemm1_kernel(const float* __restrict__ x,
                                                    const float* __restrict__ W1) {
    extern __shared__ float smem[];
    float* Ws  = smem;                        // [16][516]
    float* xs0 = smem + HID * WS_STRIDE;      // [64][64]
    float* xs1 = xs0 + G1_ROWS * G1_KC;

    int row0 = blockIdx.x * G1_ROWS;

    // stage full W (transposed) once — regular stores, covered by first sync
    for (int i = threadIdx.x; i < F_IN * HID; i += 256) {
        int k = i >> 4;
        int j = i & 15;
        Ws[j * WS_STRIDE + k] = W1[i];
    }

    // async stage of one x tile (64 rows x 64 cols) into buf
    auto stage = [&](float* buf, int kc) {
        #pragma unroll
        for (int i = threadIdx.x; i < G1_ROWS * (G1_KC / 4); i += 256) {
            int row = i >> 4;                // 16 float4 per row
            int c4  = i & 15;
            int grow = row0 + row;
            if (grow >= N_NODES) grow = N_NODES - 1;   // clamp (stores guarded)
            cp_async16((uint32_t)__cvta_generic_to_shared(&buf[row * G1_KC + c4 * 4]),
                       x + (size_t)grow * F_IN + kc + c4 * 4);
        }
    };

    stage(xs0, 0);
    CP_COMMIT();

    int warp = threadIdx.x >> 5;
    int lane = threadIdx.x & 31;
    int j    = lane & 15;
    int half = lane >> 4;

    unsigned long long acc[8];
    #pragma unroll
    for (int r = 0; r < 8; r++) acc[r] = 0ull;

    #pragma unroll
    for (int t = 0; t < G1_NT; t++) {
        float* cur = (t & 1) ? xs1 : xs0;
        if (t < G1_NT - 1) {
            stage((t & 1) ? xs0 : xs1, (t + 1) * G1_KC);
            CP_COMMIT();
            CP_WAIT(1);          // tile t's group complete
        } else {
            CP_WAIT(0);
        }
        __syncthreads();

        const float* wbase = &Ws[j * WS_STRIDE + t * G1_KC + half * 32];
        const float* xbase = &cur[warp * 8 * G1_KC + half * 32];

        #pragma unroll
        for (int kk = 0; kk < 32; kk += 4) {
            ulonglong2 w2 = *reinterpret_cast<const ulonglong2*>(wbase + kk);
            #pragma unroll
            for (int r = 0; r < 8; r++) {
                ulonglong2 xv = *reinterpret_cast<const ulonglong2*>(
                    xbase + r * G1_KC + kk);
                FMA2(acc[r], xv.x, w2.x, acc[r]);
                FMA2(acc[r], xv.y, w2.y, acc[r]);
            }
        }
        __syncthreads();         // buffer safe to overwrite next iteration
    }

    // finish: unpack pair, add halves via shfl, scale by dinv, store fp16
    #pragma unroll
    for (int r = 0; r < 8; r++) {
        float lo = __uint_as_float((unsigned)acc[r]);
        float hi = __uint_as_float((unsigned)(acc[r] >> 32));
        float a = lo + hi;
        a += __shfl_xor_sync(0xffffffffu, a, 16);
        int grow = row0 + warp * 8 + r;
        if (lane < 16 && grow < N_NODES)
            g_h1[(size_t)grow * HID + j] = __float2half(a * g_dinv[grow]);
    }
}

// -------- edge accumulation: src-only buckets, int4 = 4 edges per load ----
// lane layout: j = lane&15, p = lane>>4. fp16 h table, fp32 accumulation.
__device__ __forceinline__ float edge_accum(const __half* __restrict__ h,
                                            int beg, int end, int j, int p) {
    float a0 = 0.f, a1 = 0.f, a2 = 0.f, a3 = 0.f;
    int e = beg;
    for (; e + 7 < end; e += 8) {
        int4 v = *reinterpret_cast<const int4*>(&g_csr[e + p * 4]);
        a0 += __half2float(h[(size_t)v.x * HID + j]);
        a1 += __half2float(h[(size_t)v.y * HID + j]);
        a2 += __half2float(h[(size_t)v.z * HID + j]);
        a3 += __half2float(h[(size_t)v.w * HID + j]);
    }
    for (int t = e + p; t < end; t += 2)       // 0-7 tail edges
        a0 += __half2float(h[(size_t)g_csr[t] * HID + j]);
    float acc = (a0 + a1) + (a2 + a3);
    acc += __shfl_xor_sync(0xffffffffu, acc, 16);   // combine p-slots
    return acc;                                      // full sum on all lanes
}

// -------- layer-1: out1s = relu(dinv*(sum+hs[d]) + b1) * dinv --------
__global__ void gather1_kernel(const float* __restrict__ b1) {
    int node = (blockIdx.x * blockDim.x + threadIdx.x) >> 5;
    if (node >= N_NODES) return;
    int lane = threadIdx.x & 31;
    int j = lane & 15;
    int p = lane >> 4;

    int beg = node * BKT;
    float sum = edge_accum(g_h1, beg, beg + g_cnt[node], j, p);
    sum += __half2float(g_h1[(size_t)node * HID + j]);   // self loop (hs[d])
    float dv = g_dinv[node];
    float o = fmaxf(fmaf(dv, sum, b1[j]), 0.f) * dv;
    if (p == 0)
        g_out1[(size_t)node * HID + j] = __float2half(o);
}

// -------- layer-2 aggregation fused with GEMM2 + bias + log_softmax ------
__global__ void gather2_softmax_kernel(const float* __restrict__ W2,
                                       const float* __restrict__ b2,
                                       float* __restrict__ out) {
    __shared__ float W2s[HID * N_CLS];
    __shared__ float b2s[N_CLS];
    for (int i = threadIdx.x; i < HID * N_CLS; i += blockDim.x) W2s[i] = W2[i];
    if (threadIdx.x < N_CLS) b2s[threadIdx.x] = b2[threadIdx.x];
    __syncthreads();

    int node = (blockIdx.x * blockDim.x + threadIdx.x) >> 5;
    if (node >= N_NODES) return;
    int lane = threadIdx.x & 31;
    int j = lane & 15;
    int p = lane >> 4;

    int beg = node * BKT;
    float sum = edge_accum(g_out1, beg, beg + g_cnt[node], j, p);
    sum += __half2float(g_out1[(size_t)node * HID + j]); // self loop (out1s[d])
    float av = g_dinv[node] * sum;            // full agg on all lanes

    // av[j] replicated on lanes j and j+16. mat-vec 16x40 + log_softmax.
    bool act = lane < 20;
    int  j0  = act ? lane : 0;

    float z0 = 0.f, z1 = 0.f;
    #pragma unroll
    for (int k = 0; k < HID; k++) {
        float ak = __shfl_sync(0xffffffffu, av, k);   // lane k holds av[k]
        z0 = fmaf(ak, W2s[k * N_CLS + j0],      z0);
        z1 = fmaf(ak, W2s[k * N_CLS + j0 + 20], z1);
    }
    z0 += b2s[j0];
    z1 += b2s[j0 + 20];

    float m = act ? fmaxf(z0, z1) : -INFINITY;
    #pragma unroll
    for (int o = 16; o; o >>= 1) m = fmaxf(m, __shfl_xor_sync(0xffffffffu, m, o));
    float s = act ? (expf(z0 - m) + expf(z1 - m)) : 0.f;
    #pragma unroll
    for (int o = 16; o; o >>= 1) s += __shfl_xor_sync(0xffffffffu, s, o);
    float lse = m + logf(s);

    if (act) {
        out[(size_t)node * N_CLS + lane]      = z0 - lse;
        out[(size_t)node * N_CLS + lane + 20] = z1 - lse;
    }
}

// -------- launch --------
extern "C" void kernel_launch(void* const* d_in, const int* in_sizes, int n_in,
                              void* d_out, int out_size) {
    const float* x  = (const float*)d_in[0];
    const int*   ei = (const int*)d_in[1];     // int32 (JAX x64 disabled)
    const float* W1 = (const float*)d_in[2];
    const float* b1 = (const float*)d_in[3];
    const float* W2 = (const float*)d_in[4];
    const float* b2 = (const float*)d_in[5];
    float* out = (float*)d_out;

    cudaFuncSetAttribute(gemm1_kernel,
                         cudaFuncAttributeMaxDynamicSharedMemorySize, G1_SMEM);

    const int TB = 256;
    int nblk_nodes = (N_NODES + TB - 1) / TB;
    int nblk_edges = (E_EDGES + TB - 1) / TB;
    int nblk_gemm1 = (N_NODES + G1_ROWS - 1) / G1_ROWS;      // 1563
    int nblk_rows  = (N_NODES + (TB / 32) - 1) / (TB / 32);  // warp per node

    fill_kernel<<<nblk_edges, TB>>>(ei);          // 1
    dinv_kernel<<<nblk_nodes, TB>>>();            // 2
    gemm1_kernel<<<nblk_gemm1, TB, G1_SMEM>>>(x, W1);   // 3
    gather1_kernel<<<nblk_rows, TB>>>(b1);        // 4 -> profiled
    gather2_softmax_kernel<<<nblk_rows, TB>>>(W2, b2, out);  // 5
}

// round 17
// speedup vs baseline: 1.4676x; 1.0447x over previous
#include <cuda_runtime.h>
#include <cuda_fp16.h>
#include <cstdint>

#define N_NODES 100000
#define F_IN    512
#define HID     16
#define N_CLS   40
#define E_EDGES 3200000
#define BKT     128            // bucket capacity per node (P(overflow) ~ 1e-40)

// packed fp32x2 ops (Blackwell)
#define FMA2(d, a, b, c) \
    asm("fma.rn.f32x2 %0, %1, %2, %3;" : "=l"(d) : "l"(a), "l"(b), "l"(c))

// cp.async helpers
__device__ __forceinline__ void cp_async16(uint32_t saddr, const void* gptr) {
    asm volatile("cp.async.cg.shared.global [%0], [%1], 16;"
                 :: "r"(saddr), "l"(gptr));
}
#define CP_COMMIT() asm volatile("cp.async.commit_group;" ::: "memory")
#define CP_WAIT(n)  asm volatile("cp.async.wait_group %0;" :: "n"(n) : "memory")

// -------- device scratch (no dynamic allocation allowed) --------
__device__ __align__(16) float  g_dinv[N_NODES];
__device__ __align__(16) int    g_cur [N_NODES];     // zero-init; reset each pass
__device__ __align__(16) int    g_cnt [N_NODES];
__device__ __align__(16) int    g_csr [N_NODES * BKT];   // src-only buckets
__device__ __align__(16) __half g_h1  [N_NODES * HID];   // fp16, pre-scaled h1*dinv
__device__ __align__(16) __half g_out1[N_NODES * HID];   // fp16, pre-scaled out1*dinv

// -------- CSR fill: src index per dst bucket (zero-based cursor) --------
__global__ void fill_kernel(const int* __restrict__ ei) {
    int e = blockIdx.x * blockDim.x + threadIdx.x;
    if (e >= E_EDGES) return;
    int s = ei[e];
    int d = ei[E_EDGES + e];
    int cnt = atomicAdd(&g_cur[d], 1);
    g_csr[d * BKT + cnt] = s;
}

// -------- dinv + count snapshot + cursor reset (for next graph replay) ----
__global__ void dinv_kernel() {
    int i = blockIdx.x * blockDim.x + threadIdx.x;
    if (i < N_NODES) {
        int cnt = g_cur[i];
        g_cnt[i] = cnt;
        g_cur[i] = 0;                          // ready for next replay
        g_dinv[i] = rsqrtf((float)(cnt + 1));  // + self loop
    }
}

// -------- GEMM1: hs = (x @ W1) * dinv ; cp.async double-buffered x tiles ----
#define G1_ROWS 64
#define G1_KC   64
#define G1_NT   (F_IN / G1_KC)              // 8 tiles
#define WS_STRIDE 516                       // conflict-free LDS.128 per-j rows
#define G1_SMEM ((HID * WS_STRIDE + 2 * G1_ROWS * G1_KC) * 4)   // 65792 B

__global__ __launch_bounds__(256) void gemm1_kernel(const float* __restrict__ x,
                                                    const float* __restrict__ W1) {
    extern __shared__ float smem[];
    float* Ws  = smem;                        // [16][516]
    float* xs0 = smem + HID * WS_STRIDE;      // [64][64]
    float* xs1 = xs0 + G1_ROWS * G1_KC;

    int row0 = blockIdx.x * G1_ROWS;

    // stage full W (transposed) once — regular stores, covered by first sync
    for (int i = threadIdx.x; i < F_IN * HID; i += 256) {
        int k = i >> 4;
        int j = i & 15;
        Ws[j * WS_STRIDE + k] = W1[i];
    }

    // async stage of one x tile (64 rows x 64 cols) into buf
    auto stage = [&](float* buf, int kc) {
        #pragma unroll
        for (int i = threadIdx.x; i < G1_ROWS * (G1_KC / 4); i += 256) {
            int row = i >> 4;                // 16 float4 per row
            int c4  = i & 15;
            int grow = row0 + row;
            if (grow >= N_NODES) grow = N_NODES - 1;   // clamp (stores guarded)
            cp_async16((uint32_t)__cvta_generic_to_shared(&buf[row * G1_KC + c4 * 4]),
                       x + (size_t)grow * F_IN + kc + c4 * 4);
        }
    };

    stage(xs0, 0);
    CP_COMMIT();

    int warp = threadIdx.x >> 5;
    int lane = threadIdx.x & 31;
    int j    = lane & 15;
    int half = lane >> 4;

    unsigned long long acc[8];
    #pragma unroll
    for (int r = 0; r < 8; r++) acc[r] = 0ull;

    #pragma unroll
    for (int t = 0; t < G1_NT; t++) {
        float* cur = (t & 1) ? xs1 : xs0;
        if (t < G1_NT - 1) {
            stage((t & 1) ? xs0 : xs1, (t + 1) * G1_KC);
            CP_COMMIT();
            CP_WAIT(1);          // tile t's group complete
        } else {
            CP_WAIT(0);
        }
        __syncthreads();

        const float* wbase = &Ws[j * WS_STRIDE + t * G1_KC + half * 32];
        const float* xbase = &cur[warp * 8 * G1_KC + half * 32];

        #pragma unroll
        for (int kk = 0; kk < 32; kk += 4) {
            ulonglong2 w2 = *reinterpret_cast<const ulonglong2*>(wbase + kk);
            #pragma unroll
            for (int r = 0; r < 8; r++) {
                ulonglong2 xv = *reinterpret_cast<const ulonglong2*>(
                    xbase + r * G1_KC + kk);
                FMA2(acc[r], xv.x, w2.x, acc[r]);
                FMA2(acc[r], xv.y, w2.y, acc[r]);
            }
        }
        __syncthreads();         // buffer safe to overwrite next iteration
    }

    // finish: unpack pair, add halves via shfl, scale by dinv, store fp16
    #pragma unroll
    for (int r = 0; r < 8; r++) {
        float lo = __uint_as_float((unsigned)acc[r]);
        float hi = __uint_as_float((unsigned)(acc[r] >> 32));
        float a = lo + hi;
        a += __shfl_xor_sync(0xffffffffu, a, 16);
        int grow = row0 + warp * 8 + r;
        if (lane < 16 && grow < N_NODES)
            g_h1[(size_t)grow * HID + j] = __float2half(a * g_dinv[grow]);
    }
}

// -------- edge accumulation, half2 lanes ----------------------------------
// lane layout: j2 = lane&7 (features 2*j2, 2*j2+1), p = lane>>3 (4 slots).
// Each p-slot streams 4 edges per int4; 16 edges per warp iteration.
// Returns the p-combined float2 sum (valid on all lanes).
__device__ __forceinline__ float2 edge_accum2(const __half2* __restrict__ h2,
                                              int beg, int end, int j2, int p) {
    float f0 = 0.f, f1 = 0.f, g0 = 0.f, g1 = 0.f;
    int e = beg;
    for (; e + 15 < end; e += 16) {
        int4 v = *reinterpret_cast<const int4*>(&g_csr[e + p * 4]);
        float2 a0 = __half22float2(h2[v.x * 8 + j2]);
        float2 a1 = __half22float2(h2[v.y * 8 + j2]);
        float2 a2 = __half22float2(h2[v.z * 8 + j2]);
        float2 a3 = __half22float2(h2[v.w * 8 + j2]);
        f0 += a0.x + a2.x; f1 += a0.y + a2.y;
        g0 += a1.x + a3.x; g1 += a1.y + a3.y;
    }
    for (int t = e + p; t < end; t += 4) {     // 0-15 tail edges, 1 per p-slot
        float2 a = __half22float2(h2[g_csr[t] * 8 + j2]);
        f0 += a.x; f1 += a.y;
    }
    f0 += g0; f1 += g1;
    #pragma unroll
    for (int o = 8; o <= 16; o <<= 1) {        // combine 4 p-slots
        f0 += __shfl_xor_sync(0xffffffffu, f0, o);
        f1 += __shfl_xor_sync(0xffffffffu, f1, o);
    }
    return make_float2(f0, f1);
}

// -------- layer-1: out1s = relu(dinv*(sum+hs[d]) + b1) * dinv --------
__global__ void gather1_kernel(const float* __restrict__ b1) {
    int node = (blockIdx.x * blockDim.x + threadIdx.x) >> 5;
    if (node >= N_NODES) return;
    int lane = threadIdx.x & 31;
    int j2 = lane & 7;
    int p  = lane >> 3;

    const __half2* h2 = reinterpret_cast<const __half2*>(g_h1);
    int beg = node * BKT;
    float2 s = edge_accum2(h2, beg, beg + g_cnt[node], j2, p);
    float2 self = __half22float2(h2[node * 8 + j2]);
    s.x += self.x; s.y += self.y;              // self loop
    float dv = g_dinv[node];
    float o0 = fmaxf(fmaf(dv, s.x, b1[2 * j2]),     0.f) * dv;
    float o1 = fmaxf(fmaf(dv, s.y, b1[2 * j2 + 1]), 0.f) * dv;
    if (p == 0)
        reinterpret_cast<__half2*>(g_out1)[node * 8 + j2] =
            __floats2half2_rn(o0, o1);
}

// -------- layer-2 aggregation fused with GEMM2 + bias + log_softmax ------
__global__ void gather2_softmax_kernel(const float* __restrict__ W2,
                                       const float* __restrict__ b2,
                                       float* __restrict__ out) {
    __shared__ float W2s[HID * N_CLS];
    __shared__ float b2s[N_CLS];
    for (int i = threadIdx.x; i < HID * N_CLS; i += blockDim.x) W2s[i] = W2[i];
    if (threadIdx.x < N_CLS) b2s[threadIdx.x] = b2[threadIdx.x];
    __syncthreads();

    int node = (blockIdx.x * blockDim.x + threadIdx.x) >> 5;
    if (node >= N_NODES) return;
    int lane = threadIdx.x & 31;
    int j2 = lane & 7;
    int p  = lane >> 3;

    const __half2* h2 = reinterpret_cast<const __half2*>(g_out1);
    int beg = node * BKT;
    float2 s = edge_accum2(h2, beg, beg + g_cnt[node], j2, p);
    float2 self = __half22float2(h2[node * 8 + j2]);
    float dv = g_dinv[node];
    float s0 = dv * (s.x + self.x);
    float s1 = dv * (s.y + self.y);

    // redistribute: lane k needs av[k] = feature-k agg (k = 0..15).
    // lane k>>1 holds (s0=feat 2m, s1=feat 2m+1) for m = k>>1.
    float t0 = __shfl_sync(0xffffffffu, s0, (lane & 15) >> 1);
    float t1 = __shfl_sync(0xffffffffu, s1, (lane & 15) >> 1);
    float av = (lane & 1) ? t1 : t0;          // av[lane&15] on every lane

    // mat-vec 16x40 + log_softmax (lane k holds av[k] for k<16).
    bool act = lane < 20;
    int  j0  = act ? lane : 0;

    float z0 = 0.f, z1 = 0.f;
    #pragma unroll
    for (int k = 0; k < HID; k++) {
        float ak = __shfl_sync(0xffffffffu, av, k);
        z0 = fmaf(ak, W2s[k * N_CLS + j0],      z0);
        z1 = fmaf(ak, W2s[k * N_CLS + j0 + 20], z1);
    }
    z0 += b2s[j0];
    z1 += b2s[j0 + 20];

    float m = act ? fmaxf(z0, z1) : -INFINITY;
    #pragma unroll
    for (int o = 16; o; o >>= 1) m = fmaxf(m, __shfl_xor_sync(0xffffffffu, m, o));
    float s_ = act ? (expf(z0 - m) + expf(z1 - m)) : 0.f;
    #pragma unroll
    for (int o = 16; o; o >>= 1) s_ += __shfl_xor_sync(0xffffffffu, s_, o);
    float lse = m + logf(s_);

    if (act) {
        out[(size_t)node * N_CLS + lane]      = z0 - lse;
        out[(size_t)node * N_CLS + lane + 20] = z1 - lse;
    }
}

// -------- launch --------
extern "C" void kernel_launch(void* const* d_in, const int* in_sizes, int n_in,
                              void* d_out, int out_size) {
    const float* x  = (const float*)d_in[0];
    const int*   ei = (const int*)d_in[1];     // int32 (JAX x64 disabled)
    const float* W1 = (const float*)d_in[2];
    const float* b1 = (const float*)d_in[3];
    const float* W2 = (const float*)d_in[4];
    const float* b2 = (const float*)d_in[5];
    float* out = (float*)d_out;

    cudaFuncSetAttribute(gemm1_kernel,
                         cudaFuncAttributeMaxDynamicSharedMemorySize, G1_SMEM);

    const int TB = 256;
    int nblk_nodes = (N_NODES + TB - 1) / TB;
    int nblk_edges = (E_EDGES + TB - 1) / TB;
    int nblk_gemm1 = (N_NODES + G1_ROWS - 1) / G1_ROWS;      // 1563
    int nblk_rows  = (N_NODES + (TB / 32) - 1) / (TB / 32);  // warp per node

    fill_kernel<<<nblk_edges, TB>>>(ei);          // 1
    dinv_kernel<<<nblk_nodes, TB>>>();            // 2
    gemm1_kernel<<<nblk_gemm1, TB, G1_SMEM>>>(x, W1);   // 3
    gather1_kernel<<<nblk_rows, TB>>>(b1);        // 4 -> profiled
    gather2_softmax_kernel<<<nblk_rows, TB>>>(W2, b2, out);  // 5
}